// round 5
// baseline (speedup 1.0000x reference)
#include <cuda_runtime.h>

// Problem constants (fixed shapes from reference setup_inputs)
#define B 64
#define N 10000
#define D 128
#define F 4
#define CHUNKS 37                                    // 64*37 = 2368 CTAs = 16.0 exact waves on 148 SMs
#define ROWS_PER_CHUNK ((N + CHUNKS - 1) / CHUNKS)   // 271
#define LN_EPS 0.001f
#define EMB_LEN ((F + 1) * D)                        // 640
#define ROW_V (D / 4)                                // 32 float4 per row

// Deterministic partial-sum scratch: [B][CHUNKS][32] float4 (natively 16B-aligned)
__device__ float4 g_partials4[B * CHUNKS * ROW_V];
// Completion counters per batch (zero-init at load; self-resetting per launch)
__device__ int g_count[B];

// ---------------------------------------------------------------------------
// Single fused kernel: grid (CHUNKS, B) x 256 threads.
// Phase 1 (all CTAs): streaming float4 sum of H rows for (b, chunk) -> g_partials4.
// Phase 2 (last CTA per batch, threadfence+atomic election): gather + mean +
//         GEMM (640->128) + relu + layernorm -> out[b].
// ---------------------------------------------------------------------------
__global__ __launch_bounds__(256) void fused_kernel(
    const float* __restrict__ H,
    const int*   __restrict__ indice,
    const float* __restrict__ W,      // [640, 128] row-major
    const float* __restrict__ bias,   // [128]
    const float* __restrict__ gamma,  // [128]
    const float* __restrict__ beta,   // [128]
    float*       __restrict__ out)    // [B, 1, 128]
{
    const int chunk = blockIdx.x;
    const int b     = blockIdx.y;
    const int tid   = threadIdx.x;
    const int lane  = tid & 31;
    const int grp   = tid >> 5;   // 8 row groups

    // ---- all 16B-accessed shared buffers declared as float4 (native alignment) ----
    __shared__ float4 sm[256];            // phase-1 reduce
    __shared__ float4 emb4[EMB_LEN / 4];  // 640 floats
    __shared__ float4 part4[8 * ROW_V];   // 8 row-groups x 128 cols
    __shared__ int    sidx[F];
    __shared__ float  red_mu[4], red_var[4];
    __shared__ int    is_last;
    float* emb  = (float*)emb4;
    float* part = (float*)part4;

    // ================= Phase 1: streaming partial sum =================
    const int r0 = chunk * ROWS_PER_CHUNK;
    int r1 = r0 + ROWS_PER_CHUNK;
    if (r1 > N) r1 = N;

    const float4* __restrict__ Hv = (const float4*)H;

    float4 a0 = make_float4(0.f,0.f,0.f,0.f);
    float4 a1 = make_float4(0.f,0.f,0.f,0.f);
    float4 a2 = make_float4(0.f,0.f,0.f,0.f);
    float4 a3 = make_float4(0.f,0.f,0.f,0.f);

    int r = r0 + grp;
    for (; r + 24 < r1; r += 32) {
        float4 v0 = __ldcs(&Hv[((long long)b * N + r     ) * ROW_V + lane]);
        float4 v1 = __ldcs(&Hv[((long long)b * N + r +  8) * ROW_V + lane]);
        float4 v2 = __ldcs(&Hv[((long long)b * N + r + 16) * ROW_V + lane]);
        float4 v3 = __ldcs(&Hv[((long long)b * N + r + 24) * ROW_V + lane]);
        a0.x += v0.x; a0.y += v0.y; a0.z += v0.z; a0.w += v0.w;
        a1.x += v1.x; a1.y += v1.y; a1.z += v1.z; a1.w += v1.w;
        a2.x += v2.x; a2.y += v2.y; a2.z += v2.z; a2.w += v2.w;
        a3.x += v3.x; a3.y += v3.y; a3.z += v3.z; a3.w += v3.w;
    }
    for (; r < r1; r += 8) {
        float4 v0 = __ldcs(&Hv[((long long)b * N + r) * ROW_V + lane]);
        a0.x += v0.x; a0.y += v0.y; a0.z += v0.z; a0.w += v0.w;
    }
    a0.x += a1.x + a2.x + a3.x;
    a0.y += a1.y + a2.y + a3.y;
    a0.z += a1.z + a2.z + a3.z;
    a0.w += a1.w + a2.w + a3.w;

    sm[tid] = a0;
    __syncthreads();

    if (tid < 32) {
        float4 s = sm[lane];
        #pragma unroll
        for (int g = 1; g < 8; g++) {
            float4 v = sm[g * 32 + lane];
            s.x += v.x; s.y += v.y; s.z += v.z; s.w += v.w;
        }
        g_partials4[(b * CHUNKS + chunk) * ROW_V + lane] = s;
    }
    __syncthreads();

    // ================= last-CTA election =================
    if (tid == 0) {
        __threadfence();  // make our partial visible before bumping the counter
        int old = atomicAdd(&g_count[b], 1);
        is_last = (old == CHUNKS - 1);
        if (is_last) g_count[b] = 0;  // self-reset for next graph replay
    }
    __syncthreads();
    if (!is_last) return;

    // ================= Phase 2: fuse for batch b (256 threads) =================
    if (tid < F) sidx[tid] = __ldg(&indice[b * F + tid]);
    __syncthreads();

    // gather 4 rows (relu): 256 threads cover 2 rows per pass
    {
        const int f0 = tid >> 7;        // 0 or 1
        const int d  = tid & 127;
        #pragma unroll
        for (int p = 0; p < 2; p++) {
            const int f = f0 + 2 * p;
            emb[f * D + d] = fmaxf(__ldg(&H[((long long)b * N + sidx[f]) * D + d]), 0.0f);
        }
    }
    // mean row: threads 0..127, read peers' partials via L2 (bypass stale L1)
    if (tid < D) {
        const float* gp = (const float*)g_partials4;
        float s = 0.f;
        for (int c = 0; c < CHUNKS; c++)
            s += __ldcg(&gp[(b * CHUNKS + c) * D + tid]);
        emb[F * D + tid] = s * (1.0f / (float)N);
    }
    __syncthreads();

    // GEMM 640x128: thread (g = tid>>5, c4 = tid&31) -> rows [80g, 80g+80),
    // float4 over cols [4*c4, 4*c4+4). W stays hot in L2.
    {
        const int c4 = tid & 31;
        const int g  = tid >> 5;
        const int rb = g * 80;
        const float4* __restrict__ W4 = (const float4*)W;  // [640][32]

        float4 acc0 = make_float4(0.f,0.f,0.f,0.f);
        float4 acc1 = make_float4(0.f,0.f,0.f,0.f);
        #pragma unroll 8
        for (int j = 0; j < 80; j += 2) {
            float  e0 = emb[rb + j];
            float  e1 = emb[rb + j + 1];
            float4 w0 = __ldg(&W4[(rb + j    ) * ROW_V + c4]);
            float4 w1 = __ldg(&W4[(rb + j + 1) * ROW_V + c4]);
            acc0.x = fmaf(e0, w0.x, acc0.x); acc0.y = fmaf(e0, w0.y, acc0.y);
            acc0.z = fmaf(e0, w0.z, acc0.z); acc0.w = fmaf(e0, w0.w, acc0.w);
            acc1.x = fmaf(e1, w1.x, acc1.x); acc1.y = fmaf(e1, w1.y, acc1.y);
            acc1.z = fmaf(e1, w1.z, acc1.z); acc1.w = fmaf(e1, w1.w, acc1.w);
        }
        acc0.x += acc1.x; acc0.y += acc1.y; acc0.z += acc1.z; acc0.w += acc1.w;
        part4[g * ROW_V + c4] = acc0;
    }
    __syncthreads();

    // combine 8 partials, relu, layernorm (threads 0..127)
    float x = 0.f;
    if (tid < D) {
        x = __ldg(&bias[tid]);
        #pragma unroll
        for (int g = 0; g < 8; g++)
            x += part[g * D + tid];
        x = fmaxf(x, 0.0f);

        float v = x;
        #pragma unroll
        for (int o = 16; o > 0; o >>= 1) v += __shfl_xor_sync(0xffffffffu, v, o);
        if (lane == 0) red_mu[tid >> 5] = v;
    }
    __syncthreads();
    if (tid < D) {
        float mu = (red_mu[0] + red_mu[1] + red_mu[2] + red_mu[3]) * (1.0f / (float)D);
        float dx = x - mu;
        float v2 = dx * dx;
        #pragma unroll
        for (int o = 16; o > 0; o >>= 1) v2 += __shfl_xor_sync(0xffffffffu, v2, o);
        if (lane == 0) red_var[tid >> 5] = v2;
    }
    __syncthreads();
    if (tid < D) {
        float mu  = (red_mu[0]  + red_mu[1]  + red_mu[2]  + red_mu[3])  * (1.0f / (float)D);
        float var = (red_var[0] + red_var[1] + red_var[2] + red_var[3]) * (1.0f / (float)D);
        out[b * D + tid] = (x - mu) * rsqrtf(var + LN_EPS) * __ldg(&gamma[tid]) + __ldg(&beta[tid]);
    }
}

// ---------------------------------------------------------------------------
extern "C" void kernel_launch(void* const* d_in, const int* in_sizes, int n_in,
                              void* d_out, int out_size) {
    const float* H      = (const float*)d_in[0];
    const int*   indice = (const int*)  d_in[1];
    const float* W      = (const float*)d_in[2];
    const float* bias   = (const float*)d_in[3];
    const float* gamma  = (const float*)d_in[4];
    const float* beta   = (const float*)d_in[5];
    float* out = (float*)d_out;

    dim3 grid(CHUNKS, B);
    fused_kernel<<<grid, 256>>>(H, indice, W, bias, gamma, beta, out);
}

// round 6
// speedup vs baseline: 1.0263x; 1.0263x over previous
#include <cuda_runtime.h>

// Problem constants (fixed shapes from reference setup_inputs)
#define B 64
#define N 10000
#define D 128
#define F 4
#define CHUNKS 37                                    // 64*37 = 2368 CTAs = 16.0 exact waves on 148 SMs
#define ROWS_PER_CHUNK ((N + CHUNKS - 1) / CHUNKS)   // 271
#define LN_EPS 0.001f
#define EMB_LEN ((F + 1) * D)                        // 640
#define ROW_V (D / 4)                                // 32 float4 per row

// Deterministic partial-sum scratch: [B][CHUNKS][32] float4 (natively 16B-aligned)
__device__ float4 g_partials4[B * CHUNKS * ROW_V];
// Completion counters per batch (zero-init at load; self-resetting per launch)
__device__ int g_count[B];

// Release-acquire fetch-add: orders this CTA's prior global stores before the
// increment (release) and makes peers' stores visible after it (acquire),
// WITHOUT the gpu-scope MEMBAR + CCTL.IVALL (L1 flush) that __threadfence emits.
__device__ __forceinline__ int atom_add_acqrel(int* p, int v) {
    int old;
    asm volatile("atom.add.acq_rel.gpu.s32 %0, [%1], %2;"
                 : "=r"(old) : "l"(p), "r"(v) : "memory");
    return old;
}

// ---------------------------------------------------------------------------
// Single fused kernel: grid (CHUNKS, B) x 256 threads.
// Phase 1 (all CTAs): streaming float4 sum of H rows for (b, chunk) -> g_partials4.
// Phase 2 (last CTA per batch, elected via acq_rel atomic): gather + mean +
//         GEMM (640->128) + relu + layernorm -> out[b].
// ---------------------------------------------------------------------------
__global__ __launch_bounds__(256) void fused_kernel(
    const float* __restrict__ H,
    const int*   __restrict__ indice,
    const float* __restrict__ W,      // [640, 128] row-major
    const float* __restrict__ bias,   // [128]
    const float* __restrict__ gamma,  // [128]
    const float* __restrict__ beta,   // [128]
    float*       __restrict__ out)    // [B, 1, 128]
{
    const int chunk = blockIdx.x;
    const int b     = blockIdx.y;
    const int tid   = threadIdx.x;
    const int lane  = tid & 31;
    const int grp   = tid >> 5;   // 8 row groups

    // ---- all 16B-accessed shared buffers declared as float4 (native alignment) ----
    __shared__ float4 sm[256];            // phase-1 reduce; reused as part[] in phase 2
    __shared__ float4 emb4[EMB_LEN / 4];  // 640 floats
    __shared__ int    sidx[F];
    __shared__ float  red_mu[4], red_var[4];
    __shared__ int    is_last;
    float* emb  = (float*)emb4;
    float* part = (float*)sm;             // 8*128 floats fits in sm[256] (4KB)

    // ================= Phase 1: streaming partial sum =================
    const int r0 = chunk * ROWS_PER_CHUNK;
    int r1 = r0 + ROWS_PER_CHUNK;
    if (r1 > N) r1 = N;

    const float4* __restrict__ Hv = (const float4*)H;

    float4 a0 = make_float4(0.f,0.f,0.f,0.f);
    float4 a1 = make_float4(0.f,0.f,0.f,0.f);
    float4 a2 = make_float4(0.f,0.f,0.f,0.f);
    float4 a3 = make_float4(0.f,0.f,0.f,0.f);

    int r = r0 + grp;
    for (; r + 24 < r1; r += 32) {
        float4 v0 = __ldcs(&Hv[((long long)b * N + r     ) * ROW_V + lane]);
        float4 v1 = __ldcs(&Hv[((long long)b * N + r +  8) * ROW_V + lane]);
        float4 v2 = __ldcs(&Hv[((long long)b * N + r + 16) * ROW_V + lane]);
        float4 v3 = __ldcs(&Hv[((long long)b * N + r + 24) * ROW_V + lane]);
        a0.x += v0.x; a0.y += v0.y; a0.z += v0.z; a0.w += v0.w;
        a1.x += v1.x; a1.y += v1.y; a1.z += v1.z; a1.w += v1.w;
        a2.x += v2.x; a2.y += v2.y; a2.z += v2.z; a2.w += v2.w;
        a3.x += v3.x; a3.y += v3.y; a3.z += v3.z; a3.w += v3.w;
    }
    for (; r < r1; r += 8) {
        float4 v0 = __ldcs(&Hv[((long long)b * N + r) * ROW_V + lane]);
        a0.x += v0.x; a0.y += v0.y; a0.z += v0.z; a0.w += v0.w;
    }
    a0.x += a1.x + a2.x + a3.x;
    a0.y += a1.y + a2.y + a3.y;
    a0.z += a1.z + a2.z + a3.z;
    a0.w += a1.w + a2.w + a3.w;

    sm[tid] = a0;
    __syncthreads();

    if (tid < 32) {
        float4 s = sm[lane];
        #pragma unroll
        for (int g = 1; g < 8; g++) {
            float4 v = sm[g * 32 + lane];
            s.x += v.x; s.y += v.y; s.z += v.z; s.w += v.w;
        }
        g_partials4[(b * CHUNKS + chunk) * ROW_V + lane] = s;
    }
    __syncthreads();

    // ================= last-CTA election (no heavyweight fence) =================
    if (tid == 0) {
        int old = atom_add_acqrel(&g_count[b], 1);
        is_last = (old == CHUNKS - 1);
        if (is_last) g_count[b] = 0;  // self-reset for next graph replay
    }
    __syncthreads();
    if (!is_last) return;

    // ================= Phase 2: fuse for batch b (256 threads) =================
    if (tid < F) sidx[tid] = __ldg(&indice[b * F + tid]);
    __syncthreads();

    // gather 4 rows (relu): 256 threads cover 2 rows per pass
    {
        const int f0 = tid >> 7;        // 0 or 1
        const int d  = tid & 127;
        #pragma unroll
        for (int p = 0; p < 2; p++) {
            const int f = f0 + 2 * p;
            emb[f * D + d] = fmaxf(__ldg(&H[((long long)b * N + sidx[f]) * D + d]), 0.0f);
        }
    }
    // mean row: threads 0..127, read peers' partials via L2 (bypass stale L1)
    if (tid < D) {
        const float* gp = (const float*)g_partials4;
        float s = 0.f;
        for (int c = 0; c < CHUNKS; c++)
            s += __ldcg(&gp[(b * CHUNKS + c) * D + tid]);
        emb[F * D + tid] = s * (1.0f / (float)N);
    }
    __syncthreads();

    // GEMM 640x128: thread (g = tid>>5, c4 = tid&31) -> rows [80g, 80g+80),
    // float4 over cols [4*c4, 4*c4+4).
    {
        const int c4 = tid & 31;
        const int g  = tid >> 5;
        const int rb = g * 80;
        const float4* __restrict__ W4 = (const float4*)W;  // [640][32]

        float4 acc0 = make_float4(0.f,0.f,0.f,0.f);
        float4 acc1 = make_float4(0.f,0.f,0.f,0.f);
        #pragma unroll 8
        for (int j = 0; j < 80; j += 2) {
            float  e0 = emb[rb + j];
            float  e1 = emb[rb + j + 1];
            float4 w0 = __ldg(&W4[(rb + j    ) * ROW_V + c4]);
            float4 w1 = __ldg(&W4[(rb + j + 1) * ROW_V + c4]);
            acc0.x = fmaf(e0, w0.x, acc0.x); acc0.y = fmaf(e0, w0.y, acc0.y);
            acc0.z = fmaf(e0, w0.z, acc0.z); acc0.w = fmaf(e0, w0.w, acc0.w);
            acc1.x = fmaf(e1, w1.x, acc1.x); acc1.y = fmaf(e1, w1.y, acc1.y);
            acc1.z = fmaf(e1, w1.z, acc1.z); acc1.w = fmaf(e1, w1.w, acc1.w);
        }
        acc0.x += acc1.x; acc0.y += acc1.y; acc0.z += acc1.z; acc0.w += acc1.w;
        __syncthreads();  // done reading sm[] as phase-1 buffer? (already done) keep ordering simple
        sm[g * ROW_V + c4] = acc0;
    }
    __syncthreads();

    // combine 8 partials, relu, layernorm (threads 0..127)
    float x = 0.f;
    if (tid < D) {
        x = __ldg(&bias[tid]);
        #pragma unroll
        for (int g = 0; g < 8; g++)
            x += part[g * D + tid];
        x = fmaxf(x, 0.0f);

        float v = x;
        #pragma unroll
        for (int o = 16; o > 0; o >>= 1) v += __shfl_xor_sync(0xffffffffu, v, o);
        if (lane == 0) red_mu[tid >> 5] = v;
    }
    __syncthreads();
    if (tid < D) {
        float mu = (red_mu[0] + red_mu[1] + red_mu[2] + red_mu[3]) * (1.0f / (float)D);
        float dx = x - mu;
        float v2 = dx * dx;
        #pragma unroll
        for (int o = 16; o > 0; o >>= 1) v2 += __shfl_xor_sync(0xffffffffu, v2, o);
        if (lane == 0) red_var[tid >> 5] = v2;
    }
    __syncthreads();
    if (tid < D) {
        float mu  = (red_mu[0]  + red_mu[1]  + red_mu[2]  + red_mu[3])  * (1.0f / (float)D);
        float var = (red_var[0] + red_var[1] + red_var[2] + red_var[3]) * (1.0f / (float)D);
        out[b * D + tid] = (x - mu) * rsqrtf(var + LN_EPS) * __ldg(&gamma[tid]) + __ldg(&beta[tid]);
    }
}

// ---------------------------------------------------------------------------
extern "C" void kernel_launch(void* const* d_in, const int* in_sizes, int n_in,
                              void* d_out, int out_size) {
    const float* H      = (const float*)d_in[0];
    const int*   indice = (const int*)  d_in[1];
    const float* W      = (const float*)d_in[2];
    const float* bias   = (const float*)d_in[3];
    const float* gamma  = (const float*)d_in[4];
    const float* beta   = (const float*)d_in[5];
    float* out = (float*)d_out;

    dim3 grid(CHUNKS, B);
    fused_kernel<<<grid, 256>>>(H, indice, W, bias, gamma, beta, out);
}